// round 5
// baseline (speedup 1.0000x reference)
#include <cuda_runtime.h>
#include <math.h>

// Problem constants
#define BN   8192
#define DN   64
#define CTXN 256
#define HN   512
#define ROWS 32        // rows per CTA
#define NTHR 256
#define CTXP 34        // padded row-stride for staged context (bank-conflict-free-ish)

typedef unsigned long long u64;

// ---------------- static device scratch (no allocations allowed) -------------
__device__ __align__(16) float g_W2r[HN * HN];    // [k_in][n_out], permuted+masked
__device__ __align__(16) float g_W1r[DN * HN];    // [input d][p], permuted+masked
__device__ __align__(16) float g_WomMu[DN * HN];  // [step i][p]
__device__ __align__(16) float g_WomSc[DN * HN];  // [step i][p]
__device__ __align__(16) float g_Wcr[CTXN * HN];  // [c][p] permuted Wc
__device__ __align__(16) float g_b1r[HN];
__device__ __align__(16) float g_b2r[HN];

// ------------- degree-sorted permutation (analytic) --------------------------
// mh[h] = h % 63 + 1 ; degrees 1..8 appear 9x, 9..63 appear 8x.
// position p (sorted by degree) -> degree
__device__ __forceinline__ int degp(int p) { return (p < 72) ? (p / 9 + 1) : (p / 8); }
// position p -> original hidden index
__device__ __forceinline__ int origp(int p) {
    int d, j;
    if (p < 72) { d = p / 9 + 1; j = p - 9 * (d - 1); }
    else        { d = p / 8;     j = p - 8 * d; }
    return (d - 1) + 63 * j;
}
// number of positions with degree <= d
__device__ __forceinline__ int cntd(int d) {
    return (d <= 0) ? 0 : ((d <= 8) ? 9 * d : 8 * d + 8);
}

// ------------- packed f32x2 helpers ------------------------------------------
__device__ __forceinline__ u64 dup2(float a) {
    u64 r; asm("mov.b64 %0, {%1, %1};" : "=l"(r) : "f"(a)); return r;
}
__device__ __forceinline__ void fma2(u64& d, u64 a, u64 b) {
    asm("fma.rn.f32x2 %0, %1, %2, %0;" : "+l"(d) : "l"(a), "l"(b));
}
__device__ __forceinline__ void unpk(u64 v, float& a, float& b) {
    asm("mov.b64 {%0, %1}, %2;" : "=f"(a), "=f"(b) : "l"(v));
}

// ------------- weight preparation (masked, permuted) -------------------------
__global__ void prep_kernel(const float* __restrict__ W1, const float* __restrict__ b1,
                            const float* __restrict__ Wc, const float* __restrict__ W2,
                            const float* __restrict__ b2, const float* __restrict__ Wo) {
    int idx = blockIdx.x * blockDim.x + threadIdx.x;
    if (idx < HN * HN) {
        int k = idx / HN, n = idx % HN;           // k = input pos, n = output pos
        int dn = degp(n), dk = degp(k);
        g_W2r[idx] = (dn >= dk) ? W2[origp(n) * HN + origp(k)] : 0.f;
    }
    if (idx < DN * HN) {
        int i = idx / HN, p = idx % HN;
        int dp = degp(p), op = origp(p);
        g_W1r[idx]   = (dp >= i + 1) ? W1[op * DN + i] : 0.f;          // M1: mh >= d+1
        bool m = (dp <= i);                                            // Mo: mo=i+1 > mh
        g_WomMu[idx] = m ? Wo[i * HN + op] : 0.f;
        g_WomSc[idx] = m ? Wo[(DN + i) * HN + op] : 0.f;
    }
    if (idx < CTXN * HN) {
        int c = idx / HN, p = idx % HN;
        g_Wcr[idx] = Wc[origp(p) * CTXN + c];
    }
    if (idx < HN) {
        int op = origp(idx);
        g_b1r[idx] = b1[op];
        g_b2r[idx] = b2[op];
    }
}

// ------------- main persistent kernel ----------------------------------------
// Thread t: rg = t>>6 (rows [8rg, 8rg+8)), ul = t&63 (units [8ul, 8ul+8) = 4 f32x2 pairs)
__global__ void __launch_bounds__(NTHR, 2)
made_kernel(const float* __restrict__ ctx, const float* __restrict__ eps,
            const float* __restrict__ bo, float* __restrict__ out) {
    extern __shared__ float smem[];
    float* a1f  = smem;                   // [HN][ROWS] fp32 pre-activations (persist)
    float* zbuf = smem + HN * ROWS;       // [ROWS]
    float* red  = zbuf + ROWS;            // [8 warps][8 rows][2]

    const int t     = threadIdx.x;
    const int rg    = t >> 6;
    const int ul    = t & 63;
    const int nbase = ul << 3;
    const int lane  = t & 31;
    const int wid   = t >> 5;
    const int row0  = blockIdx.x * ROWS;

    // ---- Phase 0: stage context transposed into SMEM (stride CTXP) ----
    for (int idx = t; idx < CTXN * ROWS; idx += NTHR) {
        int r = idx >> 8;          // idx / 256
        int c = idx & 255;
        a1f[c * CTXP + r] = ctx[(row0 + r) * CTXN + c];   // coalesced global read
    }
    __syncthreads();

    // ---- Phase 1: ctx GEMM -> a1 init (acc in regs, then scatter + b1) ----
    u64 acc[4][8];
#pragma unroll
    for (int a = 0; a < 4; a++)
#pragma unroll
        for (int b = 0; b < 8; b++) acc[a][b] = 0ull;
    {
        const float* wp = g_Wcr + nbase;
        const float* hp = a1f + rg * 8;
#pragma unroll 4
        for (int c = 0; c < CTXN; c++) {
            ulonglong2 wA = *(const ulonglong2*)(wp);
            ulonglong2 wB = *(const ulonglong2*)(wp + 4);
            wp += HN;
#pragma unroll
            for (int j = 0; j < 4; j++) {
                float2 v = *(const float2*)(hp + 2 * j);
                u64 h0 = dup2(v.x), h1 = dup2(v.y);
                fma2(acc[0][2 * j], wA.x, h0); fma2(acc[1][2 * j], wA.y, h0);
                fma2(acc[2][2 * j], wB.x, h0); fma2(acc[3][2 * j], wB.y, h0);
                fma2(acc[0][2 * j + 1], wA.x, h1); fma2(acc[1][2 * j + 1], wA.y, h1);
                fma2(acc[2][2 * j + 1], wB.x, h1); fma2(acc[3][2 * j + 1], wB.y, h1);
            }
            hp += CTXP;
        }
    }
    __syncthreads();   // everyone finished reading the staged context
#pragma unroll
    for (int np = 0; np < 4; np++) {
        int n0 = nbase + 2 * np;
        float bA = g_b1r[n0], bB = g_b1r[n0 + 1];
#pragma unroll
        for (int rr = 0; rr < 8; rr++) {
            float lo, hi; unpk(acc[np][rr], lo, hi);
            int r = rg * 8 + rr;
            a1f[n0 * ROWS + r]       = lo + bA;
            a1f[(n0 + 1) * ROWS + r] = hi + bB;
        }
    }
    __syncthreads();

    // K needed for my unit block (inputs of highest-degree unit), constant
    const int myK = cntd(degp(nbase + 7));

    // ---- Phase 2: D sequential steps ----
    for (int i = 0; i < DN; i++) {
        const int ncur = cntd(i);     // h2 units feeding output column i
        float muP[8], scP[8];
#pragma unroll
        for (int r = 0; r < 8; r++) { muP[r] = 0.f; scP[r] = 0.f; }

        if (nbase < ncur) {
#pragma unroll
            for (int a = 0; a < 4; a++)
#pragma unroll
                for (int b = 0; b < 8; b++) acc[a][b] = 0ull;

            const float* wp = g_W2r + nbase;
            const float* hp = a1f + rg * 8;
#pragma unroll 4
            for (int k = 0; k < myK; k++) {
                ulonglong2 wA = *(const ulonglong2*)(wp);
                ulonglong2 wB = *(const ulonglong2*)(wp + 4);
                wp += HN;
#pragma unroll
                for (int j = 0; j < 4; j++) {
                    float2 v = *(const float2*)(hp + 2 * j);
                    float ra = fmaxf(v.x, 0.f);     // relu(a1) on the fly
                    float rb = fmaxf(v.y, 0.f);
                    u64 h0 = dup2(ra), h1 = dup2(rb);
                    fma2(acc[0][2 * j], wA.x, h0); fma2(acc[1][2 * j], wA.y, h0);
                    fma2(acc[2][2 * j], wB.x, h0); fma2(acc[3][2 * j], wB.y, h0);
                    fma2(acc[0][2 * j + 1], wA.x, h1); fma2(acc[1][2 * j + 1], wA.y, h1);
                    fma2(acc[2][2 * j + 1], wB.x, h1); fma2(acc[3][2 * j + 1], wB.y, h1);
                }
                hp += ROWS;
            }
            // fused epilogue: +b2, relu, dot with Wom mu/scale columns
            const float* wm = g_WomMu + i * HN + nbase;
            const float* ws = g_WomSc + i * HN + nbase;
#pragma unroll
            for (int np = 0; np < 4; np++) {
                int n0 = nbase + 2 * np;
                float b2a = g_b2r[n0], b2b = g_b2r[n0 + 1];
                float wma = wm[2 * np], wmb = wm[2 * np + 1];
                float wsa = ws[2 * np], wsb = ws[2 * np + 1];
#pragma unroll
                for (int rr = 0; rr < 8; rr++) {
                    float lo, hi; unpk(acc[np][rr], lo, hi);
                    float h2a = fmaxf(lo + b2a, 0.f);
                    float h2b = fmaxf(hi + b2b, 0.f);
                    muP[rr] += h2a * wma + h2b * wmb;
                    scP[rr] += h2a * wsa + h2b * wsb;
                }
            }
        }

        // warp reduce (lanes all converged here)
#pragma unroll
        for (int off = 16; off > 0; off >>= 1) {
#pragma unroll
            for (int r = 0; r < 8; r++) {
                muP[r] += __shfl_xor_sync(0xffffffffu, muP[r], off);
                scP[r] += __shfl_xor_sync(0xffffffffu, scP[r], off);
            }
        }
        if (lane == 0) {
#pragma unroll
            for (int r = 0; r < 8; r++) {
                red[wid * 16 + 2 * r]     = muP[r];
                red[wid * 16 + 2 * r + 1] = scP[r];
            }
        }
        __syncthreads();

        if (t < ROWS) {
            int r = t, rgr = r >> 3, rr = r & 7;
            float mu = red[(2 * rgr) * 16 + 2 * rr] + red[(2 * rgr + 1) * 16 + 2 * rr] + bo[i];
            float ps = red[(2 * rgr) * 16 + 2 * rr + 1] + red[(2 * rgr + 1) * 16 + 2 * rr + 1] + bo[DN + i];
            float sc = fmaxf(ps, 0.f) + log1pf(expf(-fabsf(ps)));   // softplus, stable
            int b = row0 + r;
            float z = mu + sc * eps[b * DN + i];
            out[b * DN + i]                 = z;
            out[BN * DN + b * DN + i]       = mu;
            out[2 * BN * DN + b * DN + i]   = sc;
            zbuf[r] = z;
        }
        __syncthreads();

        // rank-1 a1 update: only positions with degree >= i+1 (suffix [ncur, HN))
        {
            const int rem = HN - ncur;
            const float* w1 = g_W1r + i * HN;
            for (int idx = t; idx < rem * (ROWS / 2); idx += NTHR) {
                int p  = ncur + (idx >> 4);
                int rp = idx & 15;
                float w = w1[p];
                float2* a = (float2*)&a1f[p * ROWS + 2 * rp];
                float2 zz = *(const float2*)&zbuf[2 * rp];
                float2 av = *a;
                av.x = fmaf(zz.x, w, av.x);
                av.y = fmaf(zz.y, w, av.y);
                *a = av;
            }
        }
        __syncthreads();
    }
}

// ------------- launch ---------------------------------------------------------
extern "C" void kernel_launch(void* const* d_in, const int* in_sizes, int n_in,
                              void* d_out, int out_size) {
    (void)in_sizes; (void)n_in; (void)out_size;
    const float* ctx = (const float*)d_in[0];
    const float* eps = (const float*)d_in[1];
    const float* W1  = (const float*)d_in[2];
    const float* b1  = (const float*)d_in[3];
    const float* Wc  = (const float*)d_in[4];
    const float* W2  = (const float*)d_in[5];
    const float* b2  = (const float*)d_in[6];
    const float* Wo  = (const float*)d_in[7];
    const float* bo  = (const float*)d_in[8];
    float* out = (float*)d_out;

    prep_kernel<<<(HN * HN + 255) / 256, 256>>>(W1, b1, Wc, W2, b2, Wo);

    const int smem_bytes = (HN * ROWS + ROWS + 128) * (int)sizeof(float);  // 66176
    cudaFuncSetAttribute(made_kernel, cudaFuncAttributeMaxDynamicSharedMemorySize, smem_bytes);
    made_kernel<<<BN / ROWS, NTHR, smem_bytes>>>(ctx, eps, bo, out);
}

// round 7
// speedup vs baseline: 1.1553x; 1.1553x over previous
#include <cuda_runtime.h>
#include <math.h>

// Problem constants
#define BN   8192
#define DN   64
#define CTXN 256
#define HN   512
#define ROWS 32        // rows per CTA
#define NTHR 256
#define CTXP 36        // padded row-stride for staged context (144B, 16B-aligned!)
#define CH   256       // k-chunk size for relu staging

typedef unsigned long long u64;

// ---------------- static device scratch (no allocations allowed) -------------
__device__ __align__(16) float g_W2r[HN * HN];    // [k_in][n_out], permuted+masked
__device__ __align__(16) float g_W1r[DN * HN];    // [input d][p], permuted+masked
__device__ __align__(16) float g_WomMu[DN * HN];  // [step i][p]
__device__ __align__(16) float g_WomSc[DN * HN];  // [step i][p]
__device__ __align__(16) float g_Wcr[CTXN * HN];  // [c][p] permuted Wc
__device__ __align__(16) float g_b1r[HN];
__device__ __align__(16) float g_b2r[HN];

// ------------- degree-sorted permutation (analytic) --------------------------
// mh[h] = h % 63 + 1 ; degrees 1..8 appear 9x, 9..63 appear 8x.
__device__ __forceinline__ int degp(int p) { return (p < 72) ? (p / 9 + 1) : (p / 8); }
__device__ __forceinline__ int origp(int p) {
    int d, j;
    if (p < 72) { d = p / 9 + 1; j = p - 9 * (d - 1); }
    else        { d = p / 8;     j = p - 8 * d; }
    return (d - 1) + 63 * j;
}
__device__ __forceinline__ int cntd(int d) {
    return (d <= 0) ? 0 : ((d <= 8) ? 9 * d : 8 * d + 8);
}

// ------------- packed f32x2 helpers ------------------------------------------
__device__ __forceinline__ u64 dup2(float a) {
    u64 r; asm("mov.b64 %0, {%1, %1};" : "=l"(r) : "f"(a)); return r;
}
__device__ __forceinline__ void fma2(u64& d, u64 a, u64 b) {
    asm("fma.rn.f32x2 %0, %1, %2, %0;" : "+l"(d) : "l"(a), "l"(b));
}
__device__ __forceinline__ void unpk(u64 v, float& a, float& b) {
    asm("mov.b64 {%0, %1}, %2;" : "=f"(a), "=f"(b) : "l"(v));
}

// ------------- weight preparation (masked, permuted) -------------------------
__global__ void prep_kernel(const float* __restrict__ W1, const float* __restrict__ b1,
                            const float* __restrict__ Wc, const float* __restrict__ W2,
                            const float* __restrict__ b2, const float* __restrict__ Wo) {
    int idx = blockIdx.x * blockDim.x + threadIdx.x;
    if (idx < HN * HN) {
        int k = idx / HN, n = idx % HN;
        int dn = degp(n), dk = degp(k);
        g_W2r[idx] = (dn >= dk) ? W2[origp(n) * HN + origp(k)] : 0.f;
    }
    if (idx < DN * HN) {
        int i = idx / HN, p = idx % HN;
        int dp = degp(p), op = origp(p);
        g_W1r[idx]   = (dp >= i + 1) ? W1[op * DN + i] : 0.f;
        bool m = (dp <= i);
        g_WomMu[idx] = m ? Wo[i * HN + op] : 0.f;
        g_WomSc[idx] = m ? Wo[(DN + i) * HN + op] : 0.f;
    }
    if (idx < CTXN * HN) {
        int c = idx / HN, p = idx % HN;
        g_Wcr[idx] = Wc[origp(p) * CTXN + c];
    }
    if (idx < HN) {
        int op = origp(idx);
        g_b1r[idx] = b1[op];
        g_b2r[idx] = b2[op];
    }
}

// ------------- main persistent kernel ----------------------------------------
// Warp wid -> degree block blk (paired so SMSP s gets blocks s and 7-s).
// lane = rg*8 + ull : rows [rg*8, rg*8+8), units [blk*64 + ull*8, +8).
__global__ void __launch_bounds__(NTHR, 2)
made_kernel(const float* __restrict__ ctx, const float* __restrict__ eps,
            const float* __restrict__ bo, float* __restrict__ out) {
    extern __shared__ float smem[];
    float* a1f  = smem;                    // [HN][ROWS] pre-activations (persist)
    float* r1c  = smem + HN * ROWS;        // [CH][ROWS] relu'd chunk
    float* zbuf = r1c + CH * ROWS;         // [ROWS]
    float* red  = zbuf + ROWS;             // [8 wid][4 rg][8 rr][2]

    const int t    = threadIdx.x;
    const int wid  = t >> 5;
    const int lane = t & 31;
    const int rg   = lane >> 3;
    const int ull  = lane & 7;
    const int blk  = (wid < 4) ? wid : (11 - wid);   // SMSP pairing (b, 7-b)
    const int nbase = blk * 64 + ull * 8;
    const int r0t   = rg * 8;
    const int row0  = blockIdx.x * ROWS;
    const int KW    = cntd(degp(blk * 64 + 63));     // nonzero-K bound for this block

    // ---- Phase 0: stage context transposed into SMEM (stride CTXP=36) ----
    for (int idx = t; idx < CTXN * ROWS; idx += NTHR) {
        int r = idx >> 8;
        int c = idx & 255;
        a1f[c * CTXP + r] = ctx[(row0 + r) * CTXN + c];
    }
    __syncthreads();

    // ---- Phase 1: ctx GEMM -> a1 init ----
    u64 acc[4][8];
#pragma unroll
    for (int a = 0; a < 4; a++)
#pragma unroll
        for (int b = 0; b < 8; b++) acc[a][b] = 0ull;
    {
        const float* wp = g_Wcr + nbase;
        const float* hp = a1f + r0t;
#pragma unroll 2
        for (int c = 0; c < CTXN; c++) {
            ulonglong2 wA = *(const ulonglong2*)(wp);
            ulonglong2 wB = *(const ulonglong2*)(wp + 4);
            wp += HN;
            float4 v0 = *(const float4*)(hp);
            float4 v1 = *(const float4*)(hp + 4);
            hp += CTXP;
            u64 h[8];
            h[0] = dup2(v0.x); h[1] = dup2(v0.y); h[2] = dup2(v0.z); h[3] = dup2(v0.w);
            h[4] = dup2(v1.x); h[5] = dup2(v1.y); h[6] = dup2(v1.z); h[7] = dup2(v1.w);
#pragma unroll
            for (int r = 0; r < 8; r++) {
                fma2(acc[0][r], wA.x, h[r]);
                fma2(acc[1][r], wA.y, h[r]);
                fma2(acc[2][r], wB.x, h[r]);
                fma2(acc[3][r], wB.y, h[r]);
            }
        }
    }
    __syncthreads();
#pragma unroll
    for (int up = 0; up < 4; up++) {
        int n0 = nbase + 2 * up;
        float bA = g_b1r[n0], bB = g_b1r[n0 + 1];
#pragma unroll
        for (int rr = 0; rr < 8; rr++) {
            float lo, hi; unpk(acc[up][rr], lo, hi);
            int r = r0t + rr;
            a1f[n0 * ROWS + r]       = lo + bA;
            a1f[(n0 + 1) * ROWS + r] = hi + bB;
        }
    }
    __syncthreads();

    // ---- Phase 2: D sequential steps ----
    for (int i = 0; i < DN; i++) {
        const int ncur = cntd(i);                   // units feeding output col i
        const int kmax = (ncur < HN) ? ncur : HN;   // inputs with deg <= i
        const bool act = (blk * 64 < ncur);         // warp-uniform
        const int kw   = (KW < kmax) ? KW : kmax;

        if (act) {
#pragma unroll
            for (int a = 0; a < 4; a++)
#pragma unroll
                for (int b = 0; b < 8; b++) acc[a][b] = 0ull;
        }

        for (int kc = 0; kc < kmax; kc += CH) {
            const int kend = (kc + CH < kmax) ? (kc + CH) : kmax;
            // cooperative relu staging: r1c[(k-kc)*ROWS + r] = relu(a1f[k][r])
            for (int idx = t; idx < (kend - kc) * ROWS; idx += NTHR) {
                int kk = kc + (idx >> 5);
                int r  = idx & 31;
                r1c[idx] = fmaxf(a1f[(kk << 5) + r], 0.f);
            }
            __syncthreads();

            if (act && kw > kc) {
                const int ke = (kw < kend) ? kw : kend;
                const float* wp = g_W2r + kc * HN + nbase;
                const float* hp = r1c + r0t;
#pragma unroll 2
                for (int k = kc; k < ke; k++) {
                    ulonglong2 wA = *(const ulonglong2*)(wp);
                    ulonglong2 wB = *(const ulonglong2*)(wp + 4);
                    wp += HN;
                    float4 v0 = *(const float4*)(hp);
                    float4 v1 = *(const float4*)(hp + 4);
                    hp += ROWS;
                    u64 h[8];
                    h[0] = dup2(v0.x); h[1] = dup2(v0.y); h[2] = dup2(v0.z); h[3] = dup2(v0.w);
                    h[4] = dup2(v1.x); h[5] = dup2(v1.y); h[6] = dup2(v1.z); h[7] = dup2(v1.w);
#pragma unroll
                    for (int r = 0; r < 8; r++) {
                        fma2(acc[0][r], wA.x, h[r]);
                        fma2(acc[1][r], wA.y, h[r]);
                        fma2(acc[2][r], wB.x, h[r]);
                        fma2(acc[3][r], wB.y, h[r]);
                    }
                }
            }
            __syncthreads();
        }

        // fused epilogue: +b2, relu, dot with Wom mu/scale columns
        float muP[8], scP[8];
#pragma unroll
        for (int r = 0; r < 8; r++) { muP[r] = 0.f; scP[r] = 0.f; }
        if (act) {
            const float* wm = g_WomMu + i * HN + nbase;
            const float* ws = g_WomSc + i * HN + nbase;
#pragma unroll
            for (int up = 0; up < 4; up++) {
                int n0 = nbase + 2 * up;
                float b2a = g_b2r[n0], b2b = g_b2r[n0 + 1];
                float wma = wm[2 * up], wmb = wm[2 * up + 1];
                float wsa = ws[2 * up], wsb = ws[2 * up + 1];
#pragma unroll
                for (int rr = 0; rr < 8; rr++) {
                    float lo, hi; unpk(acc[up][rr], lo, hi);
                    float h2a = fmaxf(lo + b2a, 0.f);
                    float h2b = fmaxf(hi + b2b, 0.f);
                    muP[rr] += h2a * wma + h2b * wmb;
                    scP[rr] += h2a * wsa + h2b * wsb;
                }
            }
        }
        // reduce over ull lanes (8-lane groups; lanes grouped contiguously by rg)
#pragma unroll
        for (int off = 4; off > 0; off >>= 1) {
#pragma unroll
            for (int r = 0; r < 8; r++) {
                muP[r] += __shfl_xor_sync(0xffffffffu, muP[r], off);
                scP[r] += __shfl_xor_sync(0xffffffffu, scP[r], off);
            }
        }
        if (ull == 0) {
#pragma unroll
            for (int rr = 0; rr < 8; rr++) {
                red[wid * 64 + rg * 16 + 2 * rr]     = muP[rr];
                red[wid * 64 + rg * 16 + 2 * rr + 1] = scP[rr];
            }
        }
        __syncthreads();

        if (t < ROWS) {
            int r = t, rgr = r >> 3, rr = r & 7;
            float mu = bo[i], ps = bo[DN + i];
#pragma unroll
            for (int w = 0; w < 8; w++) {
                mu += red[w * 64 + rgr * 16 + 2 * rr];
                ps += red[w * 64 + rgr * 16 + 2 * rr + 1];
            }
            float sc = fmaxf(ps, 0.f) + log1pf(expf(-fabsf(ps)));   // stable softplus
            int b = row0 + r;
            float z = mu + sc * eps[b * DN + i];
            out[b * DN + i]               = z;
            out[BN * DN + b * DN + i]     = mu;
            out[2 * BN * DN + b * DN + i] = sc;
            zbuf[r] = z;
        }
        __syncthreads();

        // rank-1 a1 update: suffix positions [ncur, HN) only (deg >= i+1)
        {
            const int rem = HN - ncur;
            const float* w1 = g_W1r + i * HN;
            for (int idx = t; idx < rem * (ROWS / 2); idx += NTHR) {
                int p  = ncur + (idx >> 4);
                int rp = idx & 15;
                float w = w1[p];
                float2* a = (float2*)&a1f[p * ROWS + 2 * rp];
                float2 zz = *(const float2*)&zbuf[2 * rp];
                float2 av = *a;
                av.x = fmaf(zz.x, w, av.x);
                av.y = fmaf(zz.y, w, av.y);
                *a = av;
            }
        }
        __syncthreads();
    }
}

// ------------- launch ---------------------------------------------------------
extern "C" void kernel_launch(void* const* d_in, const int* in_sizes, int n_in,
                              void* d_out, int out_size) {
    (void)in_sizes; (void)n_in; (void)out_size;
    const float* ctx = (const float*)d_in[0];
    const float* eps = (const float*)d_in[1];
    const float* W1  = (const float*)d_in[2];
    const float* b1  = (const float*)d_in[3];
    const float* Wc  = (const float*)d_in[4];
    const float* W2  = (const float*)d_in[5];
    const float* b2  = (const float*)d_in[6];
    const float* Wo  = (const float*)d_in[7];
    const float* bo  = (const float*)d_in[8];
    float* out = (float*)d_out;

    prep_kernel<<<(HN * HN + 255) / 256, 256>>>(W1, b1, Wc, W2, b2, Wo);

    // smem: a1f 16384 + r1c 8192 + zbuf 32 + red 512 + pad
    const int smem_bytes = (HN * ROWS + CH * ROWS + ROWS + 512 + 64) * (int)sizeof(float);
    cudaFuncSetAttribute(made_kernel, cudaFuncAttributeMaxDynamicSharedMemorySize, smem_bytes);
    made_kernel<<<BN / ROWS, NTHR, smem_bytes>>>(ctx, eps, bo, out);
}

// round 9
// speedup vs baseline: 1.4789x; 1.2801x over previous
#include <cuda_runtime.h>
#include <math.h>

// Problem constants
#define BN   8192
#define DN   64
#define CTXN 256
#define HN   512
#define ROWS 32        // rows per CTA
#define NTHR 256
#define CTXP 36        // padded row-stride for staged context (144B, 16B-aligned)

typedef unsigned long long u64;

// ---------------- static device scratch (no allocations allowed) -------------
__device__ __align__(16) float g_W2r[HN * HN];    // [k_in][n_out], permuted+masked
__device__ __align__(16) float g_W1r[DN * HN];    // [input d][p], permuted+masked
__device__ __align__(16) float g_WomMu[DN * HN];  // [step i][p]
__device__ __align__(16) float g_WomSc[DN * HN];  // [step i][p]
__device__ __align__(16) float g_Wcr[CTXN * HN];  // [c][p] permuted Wc
__device__ __align__(16) float g_b1r[HN];
__device__ __align__(16) float g_b2r[HN];

// ------------- degree-sorted permutation (analytic) --------------------------
// mh[h] = h % 63 + 1 ; degrees 1..8 appear 9x, 9..63 appear 8x.
__device__ __forceinline__ int degp(int p) { return (p < 72) ? (p / 9 + 1) : (p / 8); }
__device__ __forceinline__ int origp(int p) {
    int d, j;
    if (p < 72) { d = p / 9 + 1; j = p - 9 * (d - 1); }
    else        { d = p / 8;     j = p - 8 * d; }
    return (d - 1) + 63 * j;
}
__device__ __forceinline__ int cntd(int d) {
    return (d <= 0) ? 0 : ((d <= 8) ? 9 * d : 8 * d + 8);
}

// ------------- packed f32x2 helpers ------------------------------------------
__device__ __forceinline__ u64 dup2(float a) {
    u64 r; asm("mov.b64 %0, {%1, %1};" : "=l"(r) : "f"(a)); return r;
}
__device__ __forceinline__ void fma2(u64& d, u64 a, u64 b) {
    asm("fma.rn.f32x2 %0, %1, %2, %0;" : "+l"(d) : "l"(a), "l"(b));
}
__device__ __forceinline__ void unpk(u64 v, float& a, float& b) {
    asm("mov.b64 {%0, %1}, %2;" : "=f"(a), "=f"(b) : "l"(v));
}

// ------------- weight preparation (masked, permuted) -------------------------
__global__ void prep_kernel(const float* __restrict__ W1, const float* __restrict__ b1,
                            const float* __restrict__ Wc, const float* __restrict__ W2,
                            const float* __restrict__ b2, const float* __restrict__ Wo) {
    int idx = blockIdx.x * blockDim.x + threadIdx.x;
    if (idx < HN * HN) {
        int k = idx / HN, n = idx % HN;
        int dn = degp(n), dk = degp(k);
        g_W2r[idx] = (dn >= dk) ? W2[origp(n) * HN + origp(k)] : 0.f;
    }
    if (idx < DN * HN) {
        int i = idx / HN, p = idx % HN;
        int dp = degp(p), op = origp(p);
        g_W1r[idx]   = (dp >= i + 1) ? W1[op * DN + i] : 0.f;
        bool m = (dp <= i);
        g_WomMu[idx] = m ? Wo[i * HN + op] : 0.f;
        g_WomSc[idx] = m ? Wo[(DN + i) * HN + op] : 0.f;
    }
    if (idx < CTXN * HN) {
        int c = idx / HN, p = idx % HN;
        g_Wcr[idx] = Wc[origp(p) * CTXN + c];
    }
    if (idx < HN) {
        int op = origp(idx);
        g_b1r[idx] = b1[op];
        g_b2r[idx] = b2[op];
    }
}

// 2-k compute: consumes weights (wA0,wB0) for k, (wA1,wB1) for k+1
#define COMPUTE2(wA0, wB0, wA1, wB1, hp)                                     \
    do {                                                                     \
        float4 v0 = *(const float4*)(hp);                                    \
        float4 v1 = *(const float4*)((hp) + 4);                              \
        u64 h[8];                                                            \
        h[0]=dup2(v0.x); h[1]=dup2(v0.y); h[2]=dup2(v0.z); h[3]=dup2(v0.w);  \
        h[4]=dup2(v1.x); h[5]=dup2(v1.y); h[6]=dup2(v1.z); h[7]=dup2(v1.w);  \
        _Pragma("unroll")                                                    \
        for (int r = 0; r < 8; r++) {                                        \
            fma2(acc[0][r], (wA0).x, h[r]);                                  \
            fma2(acc[1][r], (wA0).y, h[r]);                                  \
            fma2(acc[2][r], (wB0).x, h[r]);                                  \
            fma2(acc[3][r], (wB0).y, h[r]);                                  \
        }                                                                    \
        float4 w0 = *(const float4*)((hp) + ROWS);                           \
        float4 w1 = *(const float4*)((hp) + ROWS + 4);                       \
        h[0]=dup2(w0.x); h[1]=dup2(w0.y); h[2]=dup2(w0.z); h[3]=dup2(w0.w);  \
        h[4]=dup2(w1.x); h[5]=dup2(w1.y); h[6]=dup2(w1.z); h[7]=dup2(w1.w);  \
        _Pragma("unroll")                                                    \
        for (int r = 0; r < 8; r++) {                                        \
            fma2(acc[0][r], (wA1).x, h[r]);                                  \
            fma2(acc[1][r], (wA1).y, h[r]);                                  \
            fma2(acc[2][r], (wB1).x, h[r]);                                  \
            fma2(acc[3][r], (wB1).y, h[r]);                                  \
        }                                                                    \
    } while (0)

// ------------- main persistent kernel ----------------------------------------
// Warp wid -> degree block blk. Base pairing: SMSP s hosts blocks {s, 7-s}.
// Odd CTAs rotate SMSP assignment by 2 so co-resident CTAs' hot pairs land on
// different SMSPs.
// lane = rg*8 + ull : rows [rg*8, rg*8+8), units [blk*64 + ull*8, +8).
__global__ void __launch_bounds__(NTHR, 2)
made_kernel(const float* __restrict__ ctx, const float* __restrict__ eps,
            const float* __restrict__ bo, float* __restrict__ out) {
    extern __shared__ float smem[];
    float* a1f  = smem;                    // [HN][ROWS]: prefix relu'd, suffix raw
    float* zbuf = smem + HN * ROWS;        // [ROWS]
    float* red  = zbuf + ROWS;             // [8 wid][4 rg][8 rr][2]

    const int t    = threadIdx.x;
    const int wid  = t >> 5;
    const int lane = t & 31;
    const int rg   = lane >> 3;
    const int ull  = lane & 7;
    // CTA-parity SMSP rotation
    const int sp   = ((wid & 3) + ((blockIdx.x & 1) << 1)) & 3;
    const int widr = (wid & 4) | sp;
    const int blk  = (widr < 4) ? widr : (11 - widr);
    const int nbase = blk * 64 + ull * 8;
    const int r0t   = rg * 8;
    const int row0  = blockIdx.x * ROWS;
    const int KW    = cntd(degp(blk * 64 + 63));     // nonzero-K bound for block

    // ---- Phase 0: stage context transposed into SMEM (stride CTXP=36) ----
    for (int idx = t; idx < CTXN * ROWS; idx += NTHR) {
        int r = idx >> 8;
        int c = idx & 255;
        a1f[c * CTXP + r] = ctx[(row0 + r) * CTXN + c];
    }
    __syncthreads();

    // ---- Phase 1: ctx GEMM -> a1 init ----
    u64 acc[4][8];
#pragma unroll
    for (int a = 0; a < 4; a++)
#pragma unroll
        for (int b = 0; b < 8; b++) acc[a][b] = 0ull;
    {
        const float* wp = g_Wcr + nbase;
        const float* hp = a1f + r0t;
#pragma unroll 2
        for (int c = 0; c < CTXN; c++) {
            ulonglong2 wA = *(const ulonglong2*)(wp);
            ulonglong2 wB = *(const ulonglong2*)(wp + 4);
            wp += HN;
            float4 v0 = *(const float4*)(hp);
            float4 v1 = *(const float4*)(hp + 4);
            hp += CTXP;
            u64 h[8];
            h[0] = dup2(v0.x); h[1] = dup2(v0.y); h[2] = dup2(v0.z); h[3] = dup2(v0.w);
            h[4] = dup2(v1.x); h[5] = dup2(v1.y); h[6] = dup2(v1.z); h[7] = dup2(v1.w);
#pragma unroll
            for (int r = 0; r < 8; r++) {
                fma2(acc[0][r], wA.x, h[r]);
                fma2(acc[1][r], wA.y, h[r]);
                fma2(acc[2][r], wB.x, h[r]);
                fma2(acc[3][r], wB.y, h[r]);
            }
        }
    }
    __syncthreads();
#pragma unroll
    for (int up = 0; up < 4; up++) {
        int n0 = nbase + 2 * up;
        float bA = g_b1r[n0], bB = g_b1r[n0 + 1];
#pragma unroll
        for (int rr = 0; rr < 8; rr++) {
            float lo, hi; unpk(acc[up][rr], lo, hi);
            int r = r0t + rr;
            a1f[n0 * ROWS + r]       = lo + bA;
            a1f[(n0 + 1) * ROWS + r] = hi + bB;
        }
    }
    __syncthreads();

    // ---- Phase 2: D sequential steps ----
    for (int i = 0; i < DN; i++) {
        const int ncur = cntd(i);                   // units feeding output col i
        const bool act = (blk * 64 < ncur);         // warp-uniform
        const int kw   = (KW < ncur) ? KW : ncur;   // k range for this warp

        float muP[8], scP[8];
#pragma unroll
        for (int r = 0; r < 8; r++) { muP[r] = 0.f; scP[r] = 0.f; }

        if (act) {
#pragma unroll
            for (int a = 0; a < 4; a++)
#pragma unroll
                for (int b = 0; b < 8; b++) acc[a][b] = 0ull;

            const float* wp = g_W2r + nbase;
            const float* hp = a1f + r0t;
            int k = 0;
            if (kw >= 2) {
                // preload first 2-k group
                ulonglong2 cA0 = *(const ulonglong2*)(wp);
                ulonglong2 cB0 = *(const ulonglong2*)(wp + 4);
                ulonglong2 cA1 = *(const ulonglong2*)(wp + HN);
                ulonglong2 cB1 = *(const ulonglong2*)(wp + HN + 4);
                wp += 2 * HN;
                for (k = 0; k + 2 <= kw - 2; k += 2) {
                    ulonglong2 nA0 = *(const ulonglong2*)(wp);
                    ulonglong2 nB0 = *(const ulonglong2*)(wp + 4);
                    ulonglong2 nA1 = *(const ulonglong2*)(wp + HN);
                    ulonglong2 nB1 = *(const ulonglong2*)(wp + HN + 4);
                    wp += 2 * HN;
                    COMPUTE2(cA0, cB0, cA1, cB1, hp);
                    hp += 2 * ROWS;
                    cA0 = nA0; cB0 = nB0; cA1 = nA1; cB1 = nB1;
                }
                COMPUTE2(cA0, cB0, cA1, cB1, hp);
                hp += 2 * ROWS;
                k += 2;
            }
            for (; k < kw; k++) {          // scalar tail (odd kw)
                ulonglong2 wA = *(const ulonglong2*)(wp);
                ulonglong2 wB = *(const ulonglong2*)(wp + 4);
                wp += HN;
                float4 v0 = *(const float4*)(hp);
                float4 v1 = *(const float4*)(hp + 4);
                hp += ROWS;
                u64 h[8];
                h[0] = dup2(v0.x); h[1] = dup2(v0.y); h[2] = dup2(v0.z); h[3] = dup2(v0.w);
                h[4] = dup2(v1.x); h[5] = dup2(v1.y); h[6] = dup2(v1.z); h[7] = dup2(v1.w);
#pragma unroll
                for (int r = 0; r < 8; r++) {
                    fma2(acc[0][r], wA.x, h[r]);
                    fma2(acc[1][r], wA.y, h[r]);
                    fma2(acc[2][r], wB.x, h[r]);
                    fma2(acc[3][r], wB.y, h[r]);
                }
            }

            // fused epilogue: +b2, relu, dot with Wom mu/scale columns
            const float* wm = g_WomMu + i * HN + nbase;
            const float* ws = g_WomSc + i * HN + nbase;
#pragma unroll
            for (int up = 0; up < 4; up++) {
                int n0 = nbase + 2 * up;
                float b2a = g_b2r[n0], b2b = g_b2r[n0 + 1];
                float wma = wm[2 * up], wmb = wm[2 * up + 1];
                float wsa = ws[2 * up], wsb = ws[2 * up + 1];
#pragma unroll
                for (int rr = 0; rr < 8; rr++) {
                    float lo, hi; unpk(acc[up][rr], lo, hi);
                    float h2a = fmaxf(lo + b2a, 0.f);
                    float h2b = fmaxf(hi + b2b, 0.f);
                    muP[rr] += h2a * wma + h2b * wmb;
                    scP[rr] += h2a * wsa + h2b * wsb;
                }
            }
        }

        // reduce over ull lanes (low 3 bits of lane)
#pragma unroll
        for (int off = 4; off > 0; off >>= 1) {
#pragma unroll
            for (int r = 0; r < 8; r++) {
                muP[r] += __shfl_xor_sync(0xffffffffu, muP[r], off);
                scP[r] += __shfl_xor_sync(0xffffffffu, scP[r], off);
            }
        }
        if (ull == 0) {
#pragma unroll
            for (int rr = 0; rr < 8; rr++) {
                red[wid * 64 + rg * 16 + 2 * rr]     = muP[rr];
                red[wid * 64 + rg * 16 + 2 * rr + 1] = scP[rr];
            }
        }
        __syncthreads();

        if (t < ROWS) {
            int r = t, rgr = r >> 3, rr = r & 7;
            float mu = bo[i], ps = bo[DN + i];
#pragma unroll
            for (int w = 0; w < 8; w++) {
                mu += red[w * 64 + rgr * 16 + 2 * rr];
                ps += red[w * 64 + rgr * 16 + 2 * rr + 1];
            }
            float sc = fmaxf(ps, 0.f) + log1pf(expf(-fabsf(ps)));   // stable softplus
            int b = row0 + r;
            float z = mu + sc * eps[b * DN + i];
            out[b * DN + i]               = z;
            out[BN * DN + b * DN + i]     = mu;
            out[2 * BN * DN + b * DN + i] = sc;
            zbuf[r] = z;
        }
        __syncthreads();

        // rank-1 a1 update on suffix [ncur, HN); freeze-relu slice [ncur, nfreeze)
        if (i < DN - 1) {
            const int nfreeze = cntd(i + 1);
            const int rem = HN - ncur;
            const float* w1 = g_W1r + i * HN;
            for (int idx = t; idx < rem * (ROWS / 2); idx += NTHR) {
                int p  = ncur + (idx >> 4);
                int rp = idx & 15;
                float w = w1[p];
                float2* a = (float2*)&a1f[p * ROWS + 2 * rp];
                float2 zz = *(const float2*)&zbuf[2 * rp];
                float2 av = *a;
                av.x = fmaf(zz.x, w, av.x);
                av.y = fmaf(zz.y, w, av.y);
                if (p < nfreeze) {          // this position freezes now: apply relu
                    av.x = fmaxf(av.x, 0.f);
                    av.y = fmaxf(av.y, 0.f);
                }
                *a = av;
            }
            __syncthreads();
        }
    }
}

// ------------- launch ---------------------------------------------------------
extern "C" void kernel_launch(void* const* d_in, const int* in_sizes, int n_in,
                              void* d_out, int out_size) {
    (void)in_sizes; (void)n_in; (void)out_size;
    const float* ctx = (const float*)d_in[0];
    const float* eps = (const float*)d_in[1];
    const float* W1  = (const float*)d_in[2];
    const float* b1  = (const float*)d_in[3];
    const float* Wc  = (const float*)d_in[4];
    const float* W2  = (const float*)d_in[5];
    const float* b2  = (const float*)d_in[6];
    const float* Wo  = (const float*)d_in[7];
    const float* bo  = (const float*)d_in[8];
    float* out = (float*)d_out;

    prep_kernel<<<(HN * HN + 255) / 256, 256>>>(W1, b1, Wc, W2, b2, Wo);

    // smem: a1f 16384 + zbuf 32 + red 512 + pad
    const int smem_bytes = (HN * ROWS + ROWS + 512 + 64) * (int)sizeof(float);
    cudaFuncSetAttribute(made_kernel, cudaFuncAttributeMaxDynamicSharedMemorySize, smem_bytes);
    made_kernel<<<BN / ROWS, NTHR, smem_bytes>>>(ctx, eps, bo, out);
}